// round 12
// baseline (speedup 1.0000x reference)
#include <cuda_runtime.h>
#include <math.h>

#define HW   4096
#define NC1  32
#define NC2  64
#define NFC1 512

// ---------------- scratch (static __device__, no allocation) ----------------
__device__ float  d_M1[NC1 * HW];                  // |FFT2(pad(w1))|     0.5 MB
__device__ float  d_A2[NC2 * HW];                  // layer-2 magnitude     1 MB
__device__ float  d_G2[10 * NC2 * HW];             // fc2@fc1 collapsed  10.5 MB
__device__ float  d_H[10 * HW];                    // final hw-map        160 KB
__device__ float  d_biasv[10];                     // fc2b + fc2w@fc1b
__device__ int    d_flag;                          // M1-done counter (0 at rest)

// ============ fused: prep [0,524) | G2 stream [524,780) | A2 [780,1036) =====
__global__ void __launch_bounds__(256, 3) k_fused(
        const float* __restrict__ w1r, const float* __restrict__ w1i,
        const float* __restrict__ w2r, const float* __restrict__ w2i,
        const float* __restrict__ fc1w, const float* __restrict__ fc2w,
        const float* __restrict__ fc1b, const float* __restrict__ fc2b,
        float* __restrict__ out) {
    __shared__ __align__(16) char sbuf[24576];
    const int bx = blockIdx.x;
    const int tx = threadIdx.x;

    if (bx < 512) {
        // ---------------- M1[i,hw] = |sum_{a,b} w1[i,a,b] tw(ua+vb)| --------
        float* twr = (float*)sbuf;       // 64
        float* twi = twr + 64;           // 64
        float* wr  = twi + 64;           // 25
        float* wi  = wr + 32;            // 25
        if (tx < 64) {
            float s, c;
            sincosf(-6.283185307179586f * (float)tx / 64.0f, &s, &c);
            twr[tx] = c; twi[tx] = s;
        }
        const int i = bx >> 4, tile = bx & 15;
        if (tx < 25) { wr[tx] = w1r[i * 25 + tx]; wi[tx] = w1i[i * 25 + tx]; }
        __syncthreads();
        const int hw = tile * 256 + tx;
        const int u = hw >> 6, v = hw & 63;
        float re = 0.f, im = 0.f;
#pragma unroll
        for (int a = 0; a < 5; a++)
#pragma unroll
            for (int b = 0; b < 5; b++) {
                const int idx = (u * a + v * b) & 63;
                const float tr = twr[idx], ti = twi[idx];
                const float r = wr[a * 5 + b], q = wi[a * 5 + b];
                re += r * tr - q * ti;
                im += r * ti + q * tr;
            }
        d_M1[i * HW + hw] = sqrtf(re * re + im * im);
        __syncthreads();
        __threadfence();
        if (tx == 0) atomicAdd(&d_flag, 1);
    } else if (bx == 512) {
        // ---------------- bias ---------------------------------------------
        const int w = tx >> 5, lane = tx & 31;
        for (int c = w; c < 10; c += 8) {
            float s = 0.f;
            for (int f = lane; f < NFC1; f += 32)
                s += fc2w[c * NFC1 + f] * fc1b[f];
#pragma unroll
            for (int off = 16; off > 0; off >>= 1)
                s += __shfl_down_sync(0xffffffffu, s, off);
            if (lane == 0) d_biasv[c] = s + fc2b[c];
        }
    } else if (bx < 523) {
        // ---------------- zero H -------------------------------------------
        const int base = (bx - 513) * 4096;
#pragma unroll
        for (int k = 0; k < 16; k++) d_H[base + k * 256 + tx] = 0.f;
    } else if (bx == 523) {
        // ---------------- zero out -----------------------------------------
        for (int i = tx; i < 320; i += 256) out[i] = 0.f;
    } else if (bx < 780) {
        // ---------------- G2 stream: G2[c,o,hw] = sum_f fc2[c,f]*fc1[f,o,hw]
        const int idx = bx - 524;
        const int o = idx >> 2, tile = idx & 3;
        float* fc2s = (float*)sbuf;                  // [512][12] padded rows
        for (int i = tx; i < 5120; i += 256) {
            const int f = i / 10, c = i - f * 10;
            fc2s[f * 12 + c] = fc2w[c * NFC1 + f];
        }
        __syncthreads();
        const int col = tile * 256 + tx;             // [0,1024) float4 cols
        const float4* __restrict__ w = (const float4*)fc1w;
        float4 acc[10];
#pragma unroll
        for (int c = 0; c < 10; c++) acc[c] = make_float4(0.f, 0.f, 0.f, 0.f);
#pragma unroll 4
        for (int f = 0; f < 512; f++) {
            const float4 wv = __ldcs(&w[(size_t)f * 65536 + o * 1024 + col]);
            const float4* fr = (const float4*)&fc2s[f * 12];
            const float4 sA = fr[0];
            const float4 sB = fr[1];
            const float2 sC = ((const float2*)fr)[4];
            acc[0].x += sA.x * wv.x; acc[0].y += sA.x * wv.y; acc[0].z += sA.x * wv.z; acc[0].w += sA.x * wv.w;
            acc[1].x += sA.y * wv.x; acc[1].y += sA.y * wv.y; acc[1].z += sA.y * wv.z; acc[1].w += sA.y * wv.w;
            acc[2].x += sA.z * wv.x; acc[2].y += sA.z * wv.y; acc[2].z += sA.z * wv.z; acc[2].w += sA.z * wv.w;
            acc[3].x += sA.w * wv.x; acc[3].y += sA.w * wv.y; acc[3].z += sA.w * wv.z; acc[3].w += sA.w * wv.w;
            acc[4].x += sB.x * wv.x; acc[4].y += sB.x * wv.y; acc[4].z += sB.x * wv.z; acc[4].w += sB.x * wv.w;
            acc[5].x += sB.y * wv.x; acc[5].y += sB.y * wv.y; acc[5].z += sB.y * wv.z; acc[5].w += sB.y * wv.w;
            acc[6].x += sB.z * wv.x; acc[6].y += sB.z * wv.y; acc[6].z += sB.z * wv.z; acc[6].w += sB.z * wv.w;
            acc[7].x += sB.w * wv.x; acc[7].y += sB.w * wv.y; acc[7].z += sB.w * wv.z; acc[7].w += sB.w * wv.w;
            acc[8].x += sC.x * wv.x; acc[8].y += sC.x * wv.y; acc[8].z += sC.x * wv.z; acc[8].w += sC.x * wv.w;
            acc[9].x += sC.y * wv.x; acc[9].y += sC.y * wv.y; acc[9].z += sC.y * wv.z; acc[9].w += sC.y * wv.w;
        }
        float4* __restrict__ g2 = (float4*)d_G2;
#pragma unroll
        for (int c = 0; c < 10; c++)
            g2[(size_t)(c * 64 + o) * 1024 + col] = acc[c];
    } else {
        // ---------------- A2 (spins on M1 completion) ----------------------
        const int idx = bx - 780;
        const int bxu = idx & 3, o = idx >> 2;
        float2* Ts = (float2*)sbuf;                  // 8*320 float2 = 20480 B
        float* twr = (float*)(sbuf + 20480);
        float* twi = twr + 64;
        if (tx == 0) {
            while (atomicAdd(&d_flag, 0) < 512) __nanosleep(200);
        }
        __syncthreads();
        __threadfence();
        if (tx < 64) {
            float s, c;
            sincosf(-6.283185307179586f * (float)tx / 64.0f, &s, &c);
            twr[tx] = c; twi[tx] = s;
        }
        __syncthreads();
        const int du = tx >> 6, v = tx & 63;
        const int u0 = bxu * 4 + du;
        float tur[5], tui[5];
#pragma unroll
        for (int a = 0; a < 5; a++) {
            const int k = (u0 * a) & 63;
            tur[a] = twr[k]; tui[a] = twi[k];
        }
        float re0 = 0.f, im0 = 0.f, re1 = 0.f, im1 = 0.f;
        float re2 = 0.f, im2 = 0.f, re3 = 0.f, im3 = 0.f;
        const int hwb = u0 * 64 + v;
        for (int c = 0; c < 4; c++) {
            __syncthreads();
            for (int i2 = tx; i2 < 8 * 320; i2 += 256) {
                const int ii = i2 / 320;
                const int r = i2 - ii * 320;
                const int a = r >> 6, vv = r & 63;
                const int oi = o * NC1 + c * 8 + ii;
                float re = 0.f, im = 0.f;
#pragma unroll
                for (int b = 0; b < 5; b++) {
                    const int k = (vv * b) & 63;
                    const float rr = w2r[oi * 25 + a * 5 + b];
                    const float qq = w2i[oi * 25 + a * 5 + b];
                    re += rr * twr[k] - qq * twi[k];
                    im += rr * twi[k] + qq * twr[k];
                }
                Ts[i2] = make_float2(re, im);
            }
            __syncthreads();
#pragma unroll
            for (int ii = 0; ii < 8; ii++) {
                const int ig = c * 8 + ii;
                const float m0 = d_M1[ig * HW + hwb];
                const float m1 = d_M1[ig * HW + hwb + 1024];
                const float m2 = d_M1[ig * HW + hwb + 2048];
                const float m3 = d_M1[ig * HW + hwb + 3072];
                float kr0 = 0.f, ki0 = 0.f, kr1 = 0.f, ki1 = 0.f;
                float kr2 = 0.f, ki2 = 0.f, kr3 = 0.f, ki3 = 0.f;
#pragma unroll
                for (int a = 0; a < 5; a++) {
                    const float2 tt = Ts[ii * 320 + a * 64 + v];
                    const float pr = tur[a] * tt.x - tui[a] * tt.y;
                    const float pi = tur[a] * tt.y + tui[a] * tt.x;
                    kr0 += pr; ki0 += pi;
                    switch (a & 3) {
                        case 0: kr1 += pr; ki1 += pi;
                                kr2 += pr; ki2 += pi;
                                kr3 += pr; ki3 += pi; break;
                        case 1: kr1 += pi; ki1 -= pr;
                                kr2 -= pr; ki2 -= pi;
                                kr3 -= pi; ki3 += pr; break;
                        case 2: kr1 -= pr; ki1 -= pi;
                                kr2 += pr; ki2 += pi;
                                kr3 -= pr; ki3 -= pi; break;
                        case 3: kr1 -= pi; ki1 += pr;
                                kr2 -= pr; ki2 -= pi;
                                kr3 += pi; ki3 -= pr; break;
                    }
                }
                re0 += m0 * kr0; im0 += m0 * ki0;
                re1 += m1 * kr1; im1 += m1 * ki1;
                re2 += m2 * kr2; im2 += m2 * ki2;
                re3 += m3 * kr3; im3 += m3 * ki3;
            }
        }
        d_A2[o * HW + hwb]        = sqrtf(re0 * re0 + im0 * im0);
        d_A2[o * HW + hwb + 1024] = sqrtf(re1 * re1 + im1 * im1);
        d_A2[o * HW + hwb + 2048] = sqrtf(re2 * re2 + im2 * im2);
        d_A2[o * HW + hwb + 3072] = sqrtf(re3 * re3 + im3 * im3);
    }
}

// ---------------- k_h: H[c,hw] = sum_o A2[o,hw]*G2[c,o,hw] (L2-hot) ---------
__global__ void __launch_bounds__(128) k_h() {
    const int t = threadIdx.x;
    const int col = blockIdx.x * 128 + t;        // 8 tiles -> [0,1024) float4
    const int oc = blockIdx.y;                   // 8 chunks of 8 o
    const float4* __restrict__ a2 = (const float4*)d_A2;
    const float4* __restrict__ g2 = (const float4*)d_G2;
    float4 h[10];
#pragma unroll
    for (int c = 0; c < 10; c++) h[c] = make_float4(0.f, 0.f, 0.f, 0.f);
#pragma unroll
    for (int oo = 0; oo < 8; oo++) {
        const int o = oc * 8 + oo;
        const float4 a = a2[o * 1024 + col];
#pragma unroll
        for (int c = 0; c < 10; c++) {
            const float4 g = g2[(size_t)(c * 64 + o) * 1024 + col];
            h[c].x += a.x * g.x;
            h[c].y += a.y * g.y;
            h[c].z += a.z * g.z;
            h[c].w += a.w * g.w;
        }
    }
#pragma unroll
    for (int c = 0; c < 10; c++)
        atomicAdd(reinterpret_cast<float4*>(&d_H[c * HW]) + col, h[c]);
}

// ---------------- k_out: out[b,c] += sum_hw |x|*H; resets flag --------------
__global__ void __launch_bounds__(256) k_out(const float* __restrict__ x,
                                             float* __restrict__ out) {
    const int b = blockIdx.y;
    const int chunk = blockIdx.x;
    const int tx = threadIdx.x;
    if (chunk == 0 && b == 0 && tx == 0) d_flag = 0;   // rearm for next call
    const int hw0 = chunk * 512;
    float acc[10];
#pragma unroll
    for (int c = 0; c < 10; c++) acc[c] = 0.f;
#pragma unroll
    for (int k = 0; k < 2; k++) {
        const int hw = hw0 + k * 256 + tx;
        const float a = fabsf(x[b * HW + hw]);
#pragma unroll
        for (int c = 0; c < 10; c++) acc[c] += a * d_H[c * HW + hw];
    }
    __shared__ float red[10][256];
#pragma unroll
    for (int c = 0; c < 10; c++) red[c][tx] = acc[c];
    __syncthreads();
    for (int s = 128; s > 0; s >>= 1) {
        if (tx < s) {
#pragma unroll
            for (int c = 0; c < 10; c++) red[c][tx] += red[c][tx + s];
        }
        __syncthreads();
    }
    if (tx < 10) {
        float v = red[tx][0];
        if (chunk == 0) v += d_biasv[tx];
        atomicAdd(&out[b * 10 + tx], v);
    }
}

// ---------------- launch -----------------------------------------------------
extern "C" void kernel_launch(void* const* d_in, const int* in_sizes, int n_in,
                              void* d_out, int out_size) {
    const float* x    = (const float*)d_in[0];
    const float* w1r  = (const float*)d_in[1];
    const float* w1i  = (const float*)d_in[2];
    const float* w2r  = (const float*)d_in[3];
    const float* w2i  = (const float*)d_in[4];
    const float* fc1w = (const float*)d_in[5];
    const float* fc1b = (const float*)d_in[6];
    const float* fc2w = (const float*)d_in[7];
    const float* fc2b = (const float*)d_in[8];
    float* out = (float*)d_out;

    k_fused<<<1036, 256>>>(w1r, w1i, w2r, w2i, fc1w, fc2w, fc1b, fc2b, out);
    k_h    <<<dim3(8, 8), 128>>>();
    k_out  <<<dim3(8, 32), 256>>>(x, out);
}

// round 13
// speedup vs baseline: 1.0884x; 1.0884x over previous
#include <cuda_runtime.h>
#include <math.h>

#define HW   4096
#define NC1  32
#define NC2  64
#define NFC1 512

// ---------------- scratch (static __device__, no allocation) ----------------
__device__ float  d_M1[NC1 * HW];                  // |FFT2(pad(w1))|     0.5 MB
__device__ float  d_A2[NC2 * HW];                  // layer-2 magnitude     1 MB
__device__ float  d_H[10 * HW];                    // fc2-collapsed       160 KB
__device__ float  d_biasv[10];                     // fc2b + fc2w@fc1b
__device__ int    d_flag;                          // M1-done   (0 at rest)
__device__ int    d_flagA;                         // a2f-done  (0 at rest)
__device__ int    d_flag2;                         // k_g-done  (0 at rest)
__device__ int    d_flag3;                         // out-done  (0 at rest)

// ======== L0 k_front: prep [0,524) | A2 w/ spin [524,780), 256 thr ==========
__global__ void __launch_bounds__(256) k_front(
        const float* __restrict__ w1r, const float* __restrict__ w1i,
        const float* __restrict__ w2r, const float* __restrict__ w2i,
        const float* __restrict__ fc2w, const float* __restrict__ fc1b,
        const float* __restrict__ fc2b, float* __restrict__ out) {
    __shared__ __align__(16) char sbuf[21504];
    const int bx = blockIdx.x;
    const int tx = threadIdx.x;

    if (bx < 512) {
        // ---- M1[i,hw] = |sum_{a,b} w1[i,a,b] tw(ua+vb)| ----
        float* twr = (float*)sbuf;
        float* twi = twr + 64;
        float* wr  = twi + 64;
        float* wi  = wr + 32;
        if (tx < 64) {
            float s, c;
            sincosf(-6.283185307179586f * (float)tx / 64.0f, &s, &c);
            twr[tx] = c; twi[tx] = s;
        }
        const int i = bx >> 4, tile = bx & 15;
        if (tx < 25) { wr[tx] = w1r[i * 25 + tx]; wi[tx] = w1i[i * 25 + tx]; }
        __syncthreads();
        const int hw = tile * 256 + tx;
        const int u = hw >> 6, v = hw & 63;
        float re = 0.f, im = 0.f;
#pragma unroll
        for (int a = 0; a < 5; a++)
#pragma unroll
            for (int b = 0; b < 5; b++) {
                const int idx = (u * a + v * b) & 63;
                const float tr = twr[idx], ti = twi[idx];
                const float r = wr[a * 5 + b], q = wi[a * 5 + b];
                re += r * tr - q * ti;
                im += r * ti + q * tr;
            }
        d_M1[i * HW + hw] = sqrtf(re * re + im * im);
        __syncthreads();
        __threadfence();
        if (tx == 0) atomicAdd(&d_flag, 1);
    } else if (bx == 512) {
        // ---- bias ----
        const int w = tx >> 5, lane = tx & 31;
        for (int c = w; c < 10; c += 8) {
            float s = 0.f;
            for (int f = lane; f < NFC1; f += 32)
                s += fc2w[c * NFC1 + f] * fc1b[f];
#pragma unroll
            for (int off = 16; off > 0; off >>= 1)
                s += __shfl_down_sync(0xffffffffu, s, off);
            if (lane == 0) d_biasv[c] = s + fc2b[c];
        }
    } else if (bx < 523) {
        const int base = (bx - 513) * 4096;
#pragma unroll
        for (int k = 0; k < 16; k++) d_H[base + k * 256 + tx] = 0.f;
    } else if (bx == 523) {
        for (int i = tx; i < 320; i += 256) out[i] = 0.f;
    } else {
        // ---- A2 role (4-fold twiddle symmetry); spins on M1 completion ----
        const int idx = bx - 524;
        const int bxu = idx & 3, o = idx >> 2;
        float2* Ts = (float2*)sbuf;                   // 8*320*8 = 20480 B
        float* twr = (float*)(sbuf + 20480);          // 64
        float* twi = twr + 64;                        // 64
        if (tx == 0) {
            while (atomicAdd(&d_flag, 0) < 512) __nanosleep(200);
        }
        __syncthreads();
        __threadfence();
        if (tx < 64) {
            float s, c;
            sincosf(-6.283185307179586f * (float)tx / 64.0f, &s, &c);
            twr[tx] = c; twi[tx] = s;
        }
        __syncthreads();
        const int du = tx >> 6, v = tx & 63;
        const int u0 = bxu * 4 + du;
        float tur[5], tui[5];
#pragma unroll
        for (int a = 0; a < 5; a++) {
            const int k = (u0 * a) & 63;
            tur[a] = twr[k]; tui[a] = twi[k];
        }
        float re0 = 0.f, im0 = 0.f, re1 = 0.f, im1 = 0.f;
        float re2 = 0.f, im2 = 0.f, re3 = 0.f, im3 = 0.f;
        const int hwb = u0 * 64 + v;
        for (int c = 0; c < 4; c++) {
            __syncthreads();
            for (int i2 = tx; i2 < 8 * 320; i2 += 256) {
                const int ii = i2 / 320;
                const int r = i2 - ii * 320;
                const int a = r >> 6, vv = r & 63;
                const int oi = o * NC1 + c * 8 + ii;
                float re = 0.f, im = 0.f;
#pragma unroll
                for (int b = 0; b < 5; b++) {
                    const int k = (vv * b) & 63;
                    const float rr = w2r[oi * 25 + a * 5 + b];
                    const float qq = w2i[oi * 25 + a * 5 + b];
                    re += rr * twr[k] - qq * twi[k];
                    im += rr * twi[k] + qq * twr[k];
                }
                Ts[i2] = make_float2(re, im);
            }
            __syncthreads();
#pragma unroll
            for (int ii = 0; ii < 8; ii++) {
                const int ig = c * 8 + ii;
                const float m0 = d_M1[ig * HW + hwb];
                const float m1 = d_M1[ig * HW + hwb + 1024];
                const float m2 = d_M1[ig * HW + hwb + 2048];
                const float m3 = d_M1[ig * HW + hwb + 3072];
                float kr0 = 0.f, ki0 = 0.f, kr1 = 0.f, ki1 = 0.f;
                float kr2 = 0.f, ki2 = 0.f, kr3 = 0.f, ki3 = 0.f;
#pragma unroll
                for (int a = 0; a < 5; a++) {
                    const float2 tt = Ts[ii * 320 + a * 64 + v];
                    const float pr = tur[a] * tt.x - tui[a] * tt.y;
                    const float pi = tur[a] * tt.y + tui[a] * tt.x;
                    kr0 += pr; ki0 += pi;
                    switch (a & 3) {
                        case 0: kr1 += pr; ki1 += pi;
                                kr2 += pr; ki2 += pi;
                                kr3 += pr; ki3 += pi; break;
                        case 1: kr1 += pi; ki1 -= pr;
                                kr2 -= pr; ki2 -= pi;
                                kr3 -= pi; ki3 += pr; break;
                        case 2: kr1 -= pr; ki1 -= pi;
                                kr2 += pr; ki2 += pi;
                                kr3 -= pr; ki3 -= pi; break;
                        case 3: kr1 -= pi; ki1 += pr;
                                kr2 -= pr; ki2 -= pi;
                                kr3 += pi; ki3 -= pr; break;
                    }
                }
                re0 += m0 * kr0; im0 += m0 * ki0;
                re1 += m1 * kr1; im1 += m1 * ki1;
                re2 += m2 * kr2; im2 += m2 * ki2;
                re3 += m3 * kr3; im3 += m3 * ki3;
            }
        }
        d_A2[o * HW + hwb]        = sqrtf(re0 * re0 + im0 * im0);
        d_A2[o * HW + hwb + 1024] = sqrtf(re1 * re1 + im1 * im1);
        d_A2[o * HW + hwb + 2048] = sqrtf(re2 * re2 + im2 * im2);
        d_A2[o * HW + hwb + 3072] = sqrtf(re3 * re3 + im3 * im3);
        // ---- reset M1 flag once all 256 a2f blocks are done ----
        __syncthreads();
        if (tx == 0) {
            const int r = atomicAdd(&d_flagA, 1);
            if (r == 255) { atomicExch(&d_flag, 0); atomicExch(&d_flagA, 0); }
        }
    }
}

// ======== L1 k_gout: k_g [0,512) | k_out w/ spin [512,768), 128 thr =========
__global__ void __launch_bounds__(128) k_gout(const float* __restrict__ fc1w,
                                              const float* __restrict__ fc2w,
                                              const float* __restrict__ x,
                                              float* __restrict__ out) {
    __shared__ __align__(16) char sbuf[33344];
    const int bx = blockIdx.x;
    const int t = threadIdx.x;

    if (bx < 512) {
        // ---------------- k_g role: EXACT R10 configuration ----------------
        float4* a2s = (float4*)sbuf;                 // 16 x 128 float4 = 32 KB
        float* fc2s = (float*)(sbuf + 32768);        // [10][8]
        const int tile = bx & 7;                     // 8 tiles of 512 hw
        const int f0 = (bx >> 3) * 8;                // 64 f-chunks of 8
        if (t < 80) {
            const int c = t >> 3, f = t & 7;
            fc2s[c * 8 + f] = fc2w[c * NFC1 + f0 + f];
        }
        const float4* __restrict__ a2g = (const float4*)d_A2;
        const float4* __restrict__ w = (const float4*)fc1w;

        float4 acc[8];
#pragma unroll
        for (int f = 0; f < 8; f++) acc[f] = make_float4(0.f, 0.f, 0.f, 0.f);

        for (int oc = 0; oc < 4; oc++) {
            __syncthreads();
            for (int idx = t; idx < 16 * 128; idx += 128) {
                const int o = idx >> 7, j = idx & 127;
                a2s[idx] = a2g[(oc * 16 + o) * 1024 + tile * 128 + j];
            }
            __syncthreads();
#pragma unroll
            for (int o = 0; o < 16; o++) {
                const float4 av = a2s[o * 128 + t];
                const size_t wb = (size_t)(oc * 16 + o) * 1024 + (size_t)tile * 128 + t;
#pragma unroll
                for (int f = 0; f < 8; f++) {
                    const float4 wv = __ldcs(&w[(size_t)(f0 + f) * 65536 + wb]);
                    acc[f].x += av.x * wv.x;
                    acc[f].y += av.y * wv.y;
                    acc[f].z += av.z * wv.z;
                    acc[f].w += av.w * wv.w;
                }
            }
        }
        const int hwb = (tile * 128 + t) * 4;
#pragma unroll
        for (int c = 0; c < 10; c++) {
            float4 h = make_float4(0.f, 0.f, 0.f, 0.f);
#pragma unroll
            for (int f = 0; f < 8; f++) {
                const float s = fc2s[c * 8 + f];
                h.x += s * acc[f].x;
                h.y += s * acc[f].y;
                h.z += s * acc[f].z;
                h.w += s * acc[f].w;
            }
            atomicAdd(reinterpret_cast<float4*>(&d_H[c * HW + hwb]), h);
        }
        __threadfence();
        __syncthreads();
        if (t == 0) atomicAdd(&d_flag2, 1);
    } else {
        // ---------------- k_out role: spins on k_g completion ---------------
        float (*red)[128] = (float (*)[128])sbuf;   // [10][128]
        const int idx = bx - 512;
        const int chunk = idx & 7, b = idx >> 3;    // 8 chunks x 32 batches
        if (t == 0) {
            while (atomicAdd(&d_flag2, 0) < 512) __nanosleep(200);
        }
        __syncthreads();
        __threadfence();
        const int hw0 = chunk * 512;
        float acc[10];
#pragma unroll
        for (int c = 0; c < 10; c++) acc[c] = 0.f;
#pragma unroll
        for (int k = 0; k < 4; k++) {
            const int hw = hw0 + k * 128 + t;
            const float a = fabsf(x[b * HW + hw]);
#pragma unroll
            for (int c = 0; c < 10; c++) acc[c] += a * d_H[c * HW + hw];
        }
#pragma unroll
        for (int c = 0; c < 10; c++) red[c][t] = acc[c];
        __syncthreads();
        for (int s = 64; s > 0; s >>= 1) {
            if (t < s) {
#pragma unroll
                for (int c = 0; c < 10; c++) red[c][t] += red[c][t + s];
            }
            __syncthreads();
        }
        if (t < 10) {
            float v = red[t][0];
            if (chunk == 0) v += d_biasv[t];
            atomicAdd(&out[b * 10 + t], v);
        }
        // ---- reset k_g flag once all 256 out-blocks are done ----
        __syncthreads();
        if (t == 0) {
            const int r = atomicAdd(&d_flag3, 1);
            if (r == 255) { atomicExch(&d_flag2, 0); atomicExch(&d_flag3, 0); }
        }
    }
}

// ---------------- launch -----------------------------------------------------
extern "C" void kernel_launch(void* const* d_in, const int* in_sizes, int n_in,
                              void* d_out, int out_size) {
    const float* x    = (const float*)d_in[0];
    const float* w1r  = (const float*)d_in[1];
    const float* w1i  = (const float*)d_in[2];
    const float* w2r  = (const float*)d_in[3];
    const float* w2i  = (const float*)d_in[4];
    const float* fc1w = (const float*)d_in[5];
    const float* fc1b = (const float*)d_in[6];
    const float* fc2w = (const float*)d_in[7];
    const float* fc2b = (const float*)d_in[8];
    float* out = (float*)d_out;

    k_front<<<780, 256>>>(w1r, w1i, w2r, w2i, fc2w, fc1b, fc2b, out);
    k_gout <<<768, 128>>>(fc1w, fc2w, x, out);
}